// round 8
// baseline (speedup 1.0000x reference)
#include <cuda_runtime.h>
#include <cuda_fp16.h>
#include <math.h>
#include <stdint.h>

// ---------------------------------------------------------------------------
// AngleLinear (SphereFace A-Softmax forward, m=4, it=1) — mma.sync fp16
//   out[n,c] = clip( (x_n . w_c) / (|x_n| |w_c|), -1, 1 ) * |x_n|
//   out[n, target[n]] += (phi(c_t) - c_t) * |x_n| / (1 + lambda)
// R8: single fp16 product (A and B each single-rounded; calibrated GEMM err
// ~2.9e-4 << 1e-3 gate). W converted f32->f16 on the fly inside the GEMM
// (coalesced row reads + ldmatrix.trans) -> wtrans pass eliminated.
// ---------------------------------------------------------------------------

#define PI_F 3.141592653f
#define INVL ((float)(1.0 / (1.0 + 1500.0 / 1.1)))

#define CMAX 100352
#define DMAX 512
#define NMAX 512

__device__ float g_wnorm2[CMAX];   // per-column sum of squares
__device__ float g_xnorm[NMAX];
__device__ __half g_Ah[(size_t)NMAX * DMAX];  // x [n][d] fp16

// ---------------- PTX helpers (all sm_80-safe) ----------------
__device__ __forceinline__ uint32_t smem_u32(const void* p) {
    uint32_t a;
    asm("{ .reg .u64 t; cvta.to.shared.u64 t, %1; cvt.u32.u64 %0, t; }"
        : "=r"(a) : "l"(p));
    return a;
}
__device__ __forceinline__ void cp16(uint32_t dst, const void* src) {
    asm volatile("cp.async.cg.shared.global [%0], [%1], 16;"
                 :: "r"(dst), "l"(src));
}
#define CP_COMMIT() asm volatile("cp.async.commit_group;" ::: "memory")
#define CP_WAIT2() asm volatile("cp.async.wait_group 2;" ::: "memory")

__device__ __forceinline__ void ldsm4(uint32_t& r0, uint32_t& r1, uint32_t& r2,
                                      uint32_t& r3, uint32_t addr) {
    asm volatile("ldmatrix.sync.aligned.m8n8.x4.shared.b16 {%0,%1,%2,%3}, [%4];"
                 : "=r"(r0), "=r"(r1), "=r"(r2), "=r"(r3) : "r"(addr));
}
__device__ __forceinline__ void ldsm4t(uint32_t& r0, uint32_t& r1, uint32_t& r2,
                                       uint32_t& r3, uint32_t addr) {
    asm volatile(
        "ldmatrix.sync.aligned.m8n8.x4.trans.shared.b16 {%0,%1,%2,%3}, [%4];"
        : "=r"(r0), "=r"(r1), "=r"(r2), "=r"(r3) : "r"(addr));
}
__device__ __forceinline__ void mma16816(float* c, const uint32_t* a,
                                         uint32_t b0, uint32_t b1) {
    asm volatile(
        "mma.sync.aligned.m16n8k16.row.col.f32.f16.f16.f32 "
        "{%0,%1,%2,%3}, {%4,%5,%6,%7}, {%8,%9}, {%0,%1,%2,%3};"
        : "+f"(c[0]), "+f"(c[1]), "+f"(c[2]), "+f"(c[3])
        : "r"(a[0]), "r"(a[1]), "r"(a[2]), "r"(a[3]), "r"(b0), "r"(b1));
}

// ---------------- pre-pass kernels ----------------
__global__ void wnorm_kernel(const float* __restrict__ W, int D, int C) {
    int c = blockIdx.x * blockDim.x + threadIdx.x;
    if (c >= C) return;
    const float* p = W + c;
    float s0 = 0.f, s1 = 0.f, s2 = 0.f, s3 = 0.f;
    for (int d = 0; d < D; d += 4) {
        float v0 = __ldg(p + (size_t)d * C);
        float v1 = __ldg(p + (size_t)(d + 1) * C);
        float v2 = __ldg(p + (size_t)(d + 2) * C);
        float v3 = __ldg(p + (size_t)(d + 3) * C);
        s0 = fmaf(v0, v0, s0);
        s1 = fmaf(v1, v1, s1);
        s2 = fmaf(v2, v2, s2);
        s3 = fmaf(v3, v3, s3);
    }
    g_wnorm2[c] = (s0 + s1) + (s2 + s3);
}

__global__ void xnorm_kernel(const float* __restrict__ X, int N, int D) {
    int warp = (blockIdx.x * blockDim.x + threadIdx.x) >> 5;
    int lane = threadIdx.x & 31;
    if (warp >= N) return;
    float s = 0.0f;
    for (int d = lane; d < D; d += 32) {
        float v = X[(size_t)warp * D + d];
        s = fmaf(v, v, s);
    }
#pragma unroll
    for (int o = 16; o > 0; o >>= 1) s += __shfl_down_sync(0xffffffffu, s, o);
    if (lane == 0) g_xnorm[warp] = sqrtf(s);
}

__global__ void xconv_kernel(const float* __restrict__ X, int total) {
    int i = blockIdx.x * blockDim.x + threadIdx.x;
    if (i >= total) return;
    g_Ah[i] = __float2half_rn(X[i]);
}

// ---------------- epilogue math ----------------
__device__ __forceinline__ float epi_elem(float v, float rxn, float xn,
                                          float rwn, int c, long long tgt) {
    float cc = v * rxn * rwn;
    cc = fminf(1.0f, fmaxf(-1.0f, cc));
    float o = cc * xn;
    if ((long long)c == tgt) {
        float c2 = cc * cc;
        float cosm = fmaf(8.0f * c2, c2, fmaf(-8.0f, c2, 1.0f));
        float th = acosf(cc);
        float kf = floorf(th * (4.0f / PI_F));
        int ki = (int)kf;
        float sgn = (ki & 1) ? -1.0f : 1.0f;
        float phi = fmaf(sgn, cosm, -2.0f * kf);
        o += (phi - cc) * xn * INVL;
    }
    return o;
}

// ---------------- mma.sync GEMM + epilogue ----------------
// BM=128, BN=128, BK=32. 512 threads = 16 warps, 4x4 grid, warp tile 32x32.
// A: fp16 via cp.async, pitch 80 (normal ldmatrix).
// B: W f32 loaded coalesced, cvt->f16 in-reg (2-iter prefetch), stored [k][n]
//    pitch 272, loaded via ldmatrix.trans. 3 stages, 1 syncthreads/iter.
#define BM 128
#define BN 128
#define BK 32
#define PA 80                       // A smem pitch (64B data + 16 pad)
#define PB 272                      // B smem pitch (256B data + 16 pad)
#define OFF_A 0
#define OFF_B (BM * PA)             // 10240
#define STAGE_B (OFF_B + BK * PB)   // 18944
#define STAGES 3
#define SM_TOTAL (STAGES * STAGE_B) // 56832

__device__ __forceinline__ void ldgB(float4* r, const float* __restrict__ W,
                                     int it, int c0, int C, int tid) {
    const int k = tid >> 4;                       // 0..31
    const int cc = min(c0 + (tid & 15) * 8, C - 8);  // clamp last block col
    const float* p = W + (size_t)(it * BK + k) * C + cc;
    r[0] = *reinterpret_cast<const float4*>(p);
    r[1] = *reinterpret_cast<const float4*>(p + 4);
}
__device__ __forceinline__ void stsB(char* smem, uint32_t stage_off,
                                     const float4* r, int tid) {
    const int k = tid >> 4;
    const int ch = tid & 15;
    __half2 h0 = __floats2half2_rn(r[0].x, r[0].y);
    __half2 h1 = __floats2half2_rn(r[0].z, r[0].w);
    __half2 h2 = __floats2half2_rn(r[1].x, r[1].y);
    __half2 h3 = __floats2half2_rn(r[1].z, r[1].w);
    uint4 v;
    v.x = *reinterpret_cast<uint32_t*>(&h0);
    v.y = *reinterpret_cast<uint32_t*>(&h1);
    v.z = *reinterpret_cast<uint32_t*>(&h2);
    v.w = *reinterpret_cast<uint32_t*>(&h3);
    *reinterpret_cast<uint4*>(smem + stage_off + OFF_B + k * PB + ch * 16) = v;
}
__device__ __forceinline__ void ldA(uint32_t base, int m0, int it, int D,
                                    int tid) {
    const int r = tid >> 2;
    const int ch = tid & 3;
    cp16(base + OFF_A + (uint32_t)(r * PA + ch * 16),
         g_Ah + (size_t)(m0 + r) * D + it * BK + ch * 8);
}

__global__ void __launch_bounds__(512, 1)
gemm_epi_kernel(const float* __restrict__ W,
                const long long* __restrict__ TGT, float* __restrict__ OUT,
                int N, int D, int C) {
    extern __shared__ char smem[];
    const uint32_t sb = smem_u32(smem);
    const int tid = threadIdx.x;
    const int wid = tid >> 5;
    const int l = tid & 31;
    const int wm = wid >> 2;
    const int wn = wid & 3;
    const int m0 = blockIdx.x * BM;  // x fastest: m-tiles share W tile in L2
    const int c0 = blockIdx.y * BN;

    // A ldmatrix offsets (normal): rows 32wm + l%16, +16B col select
    const uint32_t a_off =
        (uint32_t)((32 * wm + (l & 15)) * PA + (l >> 4) * 16);
    // B ldmatrix.trans offsets: group g=l>>3: row k = (g&1)*8 + l%8,
    // col n = 32wn + (g>>1)*8. Per ks: +16 rows; per n16 group: +16 cols.
    const uint32_t b_off =
        (uint32_t)((((l >> 3) & 1) * 8 + (l & 7)) * PB +
                   (32 * wn + (l >> 4) * 8) * 2);

    float acc[2][4][4];
#pragma unroll
    for (int i = 0; i < 2; i++)
#pragma unroll
        for (int j = 0; j < 4; j++)
#pragma unroll
            for (int q = 0; q < 4; q++) acc[i][j][q] = 0.0f;

    const int iters = D / BK;  // 16
    float4 rcur[2], rnext[2];

    // prologue: B(0) straight to stage0; B(1) into regs; A(0), A(1) async
    ldgB(rcur, W, 0, c0, C, tid);
    stsB(smem, 0, rcur, tid);
    ldA(sb, m0, 0, D, tid);
    CP_COMMIT();
    ldgB(rcur, W, 1, c0, C, tid);
    ldA(sb + STAGE_B, m0, 1, D, tid);
    CP_COMMIT();

    for (int it = 0; it < iters; it++) {
        if (it + 2 < iters) ldgB(rnext, W, it + 2, c0, C, tid);
        if (it + 1 < iters)
            stsB(smem, (uint32_t)((it + 1) % STAGES) * STAGE_B, rcur, tid);
        if (it + 2 < iters)
            ldA(sb + (uint32_t)((it + 2) % STAGES) * STAGE_B, m0, it + 2, D, tid);
        CP_COMMIT();
        CP_WAIT2();          // A(it) resident (<=2 groups outstanding)
        __syncthreads();     // B(it+1)/A visible; stages safe to overwrite

        const uint32_t base = sb + (uint32_t)(it % STAGES) * STAGE_B;
#pragma unroll
        for (int ks = 0; ks < 2; ks++) {
            uint32_t ah[2][4];
            ldsm4(ah[0][0], ah[0][1], ah[0][2], ah[0][3],
                  base + OFF_A + a_off + ks * 32);
            ldsm4(ah[1][0], ah[1][1], ah[1][2], ah[1][3],
                  base + OFF_A + a_off + ks * 32 + 16 * PA);

            uint32_t bh[4][2];
            ldsm4t(bh[0][0], bh[0][1], bh[1][0], bh[1][1],
                   base + OFF_B + b_off + ks * (16 * PB));
            ldsm4t(bh[2][0], bh[2][1], bh[3][0], bh[3][1],
                   base + OFF_B + b_off + ks * (16 * PB) + 32);

#pragma unroll
            for (int i = 0; i < 2; i++)
#pragma unroll
                for (int j = 0; j < 4; j++)
                    mma16816(acc[i][j], ah[i], bh[j][0], bh[j][1]);
        }
        rcur[0] = rnext[0];
        rcur[1] = rnext[1];
    }

    // ---- epilogue ----
    const int base_m = m0 + 32 * wm + (l >> 2);
    float xns[2][2], rxns[2][2];
    long long tgs[2][2];
#pragma unroll
    for (int i = 0; i < 2; i++)
#pragma unroll
        for (int p = 0; p < 2; p++) {
            int row = base_m + 16 * i + 8 * p;  // always < N (N=512, BM exact)
            float xn = g_xnorm[row];
            xns[i][p] = xn;
            rxns[i][p] = 1.0f / xn;
            tgs[i][p] = TGT[row];
        }

#pragma unroll
    for (int j = 0; j < 4; j++) {
        const int c = c0 + 32 * wn + 8 * j + 2 * (l & 3);
        if (c >= C) continue;  // C even -> pair fully valid or fully out
        const float rw0 = rsqrtf(g_wnorm2[c]);
        const float rw1 = rsqrtf(g_wnorm2[c + 1]);
#pragma unroll
        for (int i = 0; i < 2; i++)
#pragma unroll
            for (int p = 0; p < 2; p++) {
                const int row = base_m + 16 * i + 8 * p;
                float2 o;
                o.x = epi_elem(acc[i][j][2 * p + 0], rxns[i][p], xns[i][p],
                               rw0, c, tgs[i][p]);
                o.y = epi_elem(acc[i][j][2 * p + 1], rxns[i][p], xns[i][p],
                               rw1, c + 1, tgs[i][p]);
                *reinterpret_cast<float2*>(&OUT[(size_t)row * C + c]) = o;
            }
    }
}

// ---------------------------------------------------------------------------
extern "C" void kernel_launch(void* const* d_in, const int* in_sizes, int n_in,
                              void* d_out, int out_size) {
    const float* x = (const float*)d_in[0];
    const long long* tgt = (const long long*)d_in[1];
    const float* w = (const float*)d_in[2];
    float* out = (float*)d_out;

    const int N = in_sizes[1];            // 512
    const int D = in_sizes[0] / N;        // 512
    const int C = in_sizes[2] / D;        // 100000

    xnorm_kernel<<<(N + 7) / 8, 256>>>(x, N, D);
    xconv_kernel<<<(N * D + 255) / 256, 256>>>(x, N * D);
    wnorm_kernel<<<(C + 255) / 256, 256>>>(w, D, C);

    cudaFuncSetAttribute(gemm_epi_kernel,
                         cudaFuncAttributeMaxDynamicSharedMemorySize, SM_TOTAL);
    dim3 grid((N + BM - 1) / BM, (C + BN - 1) / BN);
    gemm_epi_kernel<<<grid, 512, SM_TOTAL>>>(w, tgt, out, N, D, C);
}

// round 9
// speedup vs baseline: 1.8938x; 1.8938x over previous
#include <cuda_runtime.h>
#include <cuda_fp16.h>
#include <math.h>
#include <stdint.h>

// ---------------------------------------------------------------------------
// AngleLinear (SphereFace A-Softmax forward, m=4, it=1) — mma.sync fp16
//   out[n,c] = clip( (x_n . w_c) / (|x_n| |w_c|), -1, 1 ) * |x_n|
//   out[n, target[n]] += (phi(c_t) - c_t) * |x_n| / (1 + lambda)
// R9: single fp16 product (rel_err 3.5e-4 < 1e-3, calibrated R8), back to the
// proven cp.async + K-major-ldmatrix pipeline (R7, 67% tensor), but with
// 2 CTAs x 256 threads per SM so two pipelines interleave across barriers.
// ---------------------------------------------------------------------------

#define PI_F 3.141592653f
#define INVL ((float)(1.0 / (1.0 + 1500.0 / 1.1)))

#define CMAX 100352
#define DMAX 512
#define NMAX 512

__device__ float g_wnorm2[CMAX];   // per-column sum of squares (atomic-folded)
__device__ float g_xnorm[NMAX];
__device__ __half g_Wh[(size_t)CMAX * DMAX];  // W^T [c][d], fp16
__device__ __half g_Ah[(size_t)NMAX * DMAX];  // x [n][d], fp16

// ---------------- PTX helpers (all sm_80-safe) ----------------
__device__ __forceinline__ uint32_t smem_u32(const void* p) {
    uint32_t a;
    asm("{ .reg .u64 t; cvta.to.shared.u64 t, %1; cvt.u32.u64 %0, t; }"
        : "=r"(a) : "l"(p));
    return a;
}
__device__ __forceinline__ void cp16(uint32_t dst, const void* src) {
    asm volatile("cp.async.cg.shared.global [%0], [%1], 16;"
                 :: "r"(dst), "l"(src));
}
#define CP_COMMIT() asm volatile("cp.async.commit_group;" ::: "memory")
#define CP_WAIT1() asm volatile("cp.async.wait_group 1;" ::: "memory")

__device__ __forceinline__ void ldsm4(uint32_t& r0, uint32_t& r1, uint32_t& r2,
                                      uint32_t& r3, uint32_t addr) {
    asm volatile("ldmatrix.sync.aligned.m8n8.x4.shared.b16 {%0,%1,%2,%3}, [%4];"
                 : "=r"(r0), "=r"(r1), "=r"(r2), "=r"(r3) : "r"(addr));
}
__device__ __forceinline__ void mma16816(float* c, const uint32_t* a,
                                         uint32_t b0, uint32_t b1) {
    asm volatile(
        "mma.sync.aligned.m16n8k16.row.col.f32.f16.f16.f32 "
        "{%0,%1,%2,%3}, {%4,%5,%6,%7}, {%8,%9}, {%0,%1,%2,%3};"
        : "+f"(c[0]), "+f"(c[1]), "+f"(c[2]), "+f"(c[3])
        : "r"(a[0]), "r"(a[1]), "r"(a[2]), "r"(a[3]), "r"(b0), "r"(b1));
}

// ---------------- pre-pass kernels ----------------
__global__ void zero_kernel() {
    int i = blockIdx.x * blockDim.x + threadIdx.x;
    if (i < CMAX) g_wnorm2[i] = 0.0f;
}

__global__ void xnorm_kernel(const float* __restrict__ X, int N, int D) {
    int warp = (blockIdx.x * blockDim.x + threadIdx.x) >> 5;
    int lane = threadIdx.x & 31;
    if (warp >= N) return;
    float s = 0.0f;
    for (int d = lane; d < D; d += 32) {
        float v = X[(size_t)warp * D + d];
        s = fmaf(v, v, s);
    }
#pragma unroll
    for (int o = 16; o > 0; o >>= 1) s += __shfl_down_sync(0xffffffffu, s, o);
    if (lane == 0) g_xnorm[warp] = sqrtf(s);
}

__global__ void xconv_kernel(const float* __restrict__ X, int total) {
    int i = blockIdx.x * blockDim.x + threadIdx.x;
    if (i >= total) return;
    g_Ah[i] = __float2half_rn(X[i]);
}

// W [D,C] f32 -> W^T [C,D] fp16 (64x64 tiles through SMEM),
// with per-column sum of squares folded in (atomicAdd partials).
#define SRD_P 68
__global__ void wtrans_kernel(const float* __restrict__ W, int D, int C) {
    __shared__ float s[64][65];
    __shared__ float srd[64][SRD_P];
    const int tid = threadIdx.x;
    const int c0 = blockIdx.x * 64;
    const int d0 = blockIdx.y * 64;
#pragma unroll
    for (int i = 0; i < 16; i++) {
        int e = tid + 256 * i;
        int d = e >> 6, c = e & 63;
        float v = 0.0f;
        if (c0 + c < C) v = W[(size_t)(d0 + d) * C + (c0 + c)];
        s[d][c] = v;
    }
    __syncthreads();
    const int j = tid & 63;
#pragma unroll
    for (int i = 0; i < 16; i++) {
        int e = tid + 256 * i;
        int c = e >> 6, d = e & 63;  // c is warp-uniform per i
        int gc = c0 + c;
        float v = s[d][c];
        srd[c][j] = v * v;           // (c, j) unique per (thread, i)
        if (gc < C)
            g_Wh[(size_t)gc * D + (d0 + d)] = __float2half_rn(v);
    }
    __syncthreads();
    if (tid < 64) {
        float sum = 0.0f;
#pragma unroll
        for (int q = 0; q < 64; q++) sum += srd[tid][q];
        if (c0 + tid < C) atomicAdd(&g_wnorm2[c0 + tid], sum);
    }
}

// ---------------- epilogue math ----------------
__device__ __forceinline__ float epi_elem(float v, float rxn, float xn,
                                          float rwn, int c, long long tgt) {
    float cc = v * rxn * rwn;
    cc = fminf(1.0f, fmaxf(-1.0f, cc));
    float o = cc * xn;
    if ((long long)c == tgt) {
        float c2 = cc * cc;
        float cosm = fmaf(8.0f * c2, c2, fmaf(-8.0f, c2, 1.0f));
        float th = acosf(cc);
        float kf = floorf(th * (4.0f / PI_F));
        int ki = (int)kf;
        float sgn = (ki & 1) ? -1.0f : 1.0f;
        float phi = fmaf(sgn, cosm, -2.0f * kf);
        o += (phi - cc) * xn * INVL;
    }
    return o;
}

// ---------------- mma.sync GEMM + epilogue ----------------
// BM=128, BN=128, BK=32. 256 threads = 8 warps (4x2), warp tile 32x64.
// 2 CTAs / SM interleave across barriers. SMEM pitch 80 (conflict-free
// ldmatrix). 3-stage cp.async, 1 syncthreads per iter.
#define BM 128
#define BN 128
#define BK 32
#define PA 80
#define TILE_B (128 * PA)           // 10240 per tile (A or B)
#define STAGE_B (2 * TILE_B)        // 20480 per stage
#define STAGES 3
#define SM_TOTAL (STAGES * STAGE_B) // 61440 -> 2 CTAs/SM

#define OFF_A 0
#define OFF_B TILE_B

__device__ __forceinline__ void load_stage(uint32_t base, int m0, int c0,
                                           int it, int D, int tid) {
    const int r = tid >> 1;               // 0..127
    const int ch = (tid & 1) * 2;         // chunks {0,1} or {2,3}
#pragma unroll
    for (int q = 0; q < 2; q++) {
        const uint32_t doff = (uint32_t)(r * PA + (ch + q) * 16);
        const size_t koff = (size_t)it * BK + (ch + q) * 8;
        cp16(base + OFF_A + doff, g_Ah + (size_t)(m0 + r) * D + koff);
        cp16(base + OFF_B + doff, g_Wh + (size_t)(c0 + r) * D + koff);
    }
}

__global__ void __launch_bounds__(256, 2)
gemm_epi_kernel(const long long* __restrict__ TGT, float* __restrict__ OUT,
                int N, int D, int C) {
    extern __shared__ char smem[];
    const uint32_t sb = smem_u32(smem);
    const int tid = threadIdx.x;
    const int wid = tid >> 5;
    const int l = tid & 31;
    const int wm = wid >> 1;         // 0..3 -> rows 32*wm
    const int wn = wid & 1;          // 0..1 -> cols 64*wn
    const int m0 = blockIdx.x * BM;  // x fastest: m-tiles share W tile in L2
    const int c0 = blockIdx.y * BN;

    // A ldmatrix (normal): rows 32wm + l%16, 16B col select by l/16
    const uint32_t a_off =
        (uint32_t)((32 * wm + (l & 15)) * PA + (l >> 4) * 16);
    // B ldmatrix (K-major): rows 64wn + l%8 + 8*(l/16), col 16B by (l>>3)&1;
    // +16*PA per n16 group g.
    const uint32_t b_off =
        (uint32_t)((64 * wn + (l & 7) + ((l >> 4) << 3)) * PA +
                   ((l >> 3) & 1) * 16);

    float acc[2][8][4];
#pragma unroll
    for (int i = 0; i < 2; i++)
#pragma unroll
        for (int j = 0; j < 8; j++)
#pragma unroll
            for (int q = 0; q < 4; q++) acc[i][j][q] = 0.0f;

    const int iters = D / BK;  // 16
    load_stage(sb, m0, c0, 0, D, tid);
    CP_COMMIT();
    load_stage(sb + STAGE_B, m0, c0, 1, D, tid);
    CP_COMMIT();

    for (int it = 0; it < iters; it++) {
        CP_WAIT1();          // stage it resident
        __syncthreads();     // stage (it+2)%3 free of readers
        if (it + 2 < iters)
            load_stage(sb + (uint32_t)((it + 2) % STAGES) * STAGE_B,
                       m0, c0, it + 2, D, tid);
        CP_COMMIT();

        const uint32_t base = sb + (uint32_t)(it % STAGES) * STAGE_B;
#pragma unroll
        for (int ks = 0; ks < 2; ks++) {
            const uint32_t ko = (uint32_t)(ks * 32);
            uint32_t ah[2][4];
            ldsm4(ah[0][0], ah[0][1], ah[0][2], ah[0][3],
                  base + OFF_A + a_off + ko);
            ldsm4(ah[1][0], ah[1][1], ah[1][2], ah[1][3],
                  base + OFF_A + a_off + ko + 16 * PA);

            uint32_t bh[8][2];
#pragma unroll
            for (int g = 0; g < 4; g++)
                ldsm4(bh[2 * g][0], bh[2 * g][1], bh[2 * g + 1][0],
                      bh[2 * g + 1][1],
                      base + OFF_B + b_off + ko + (uint32_t)g * (16 * PA));

#pragma unroll
            for (int i = 0; i < 2; i++)
#pragma unroll
                for (int j = 0; j < 8; j++)
                    mma16816(acc[i][j], ah[i], bh[j][0], bh[j][1]);
        }
    }

    // ---- epilogue ----
    const int base_m = m0 + 32 * wm + (l >> 2);
    float xns[2][2], rxns[2][2];
    long long tgs[2][2];
#pragma unroll
    for (int i = 0; i < 2; i++)
#pragma unroll
        for (int p = 0; p < 2; p++) {
            int row = base_m + 16 * i + 8 * p;  // always < N (N=512, BM exact)
            float xn = g_xnorm[row];
            xns[i][p] = xn;
            rxns[i][p] = 1.0f / xn;
            tgs[i][p] = TGT[row];
        }

#pragma unroll
    for (int j = 0; j < 8; j++) {
        const int c = c0 + 64 * wn + 8 * j + 2 * (l & 3);
        if (c >= C) continue;  // C even -> pair fully valid or fully out
        const float rw0 = rsqrtf(g_wnorm2[c]);
        const float rw1 = rsqrtf(g_wnorm2[c + 1]);
#pragma unroll
        for (int i = 0; i < 2; i++)
#pragma unroll
            for (int p = 0; p < 2; p++) {
                const int row = base_m + 16 * i + 8 * p;
                float2 o;
                o.x = epi_elem(acc[i][j][2 * p + 0], rxns[i][p], xns[i][p],
                               rw0, c, tgs[i][p]);
                o.y = epi_elem(acc[i][j][2 * p + 1], rxns[i][p], xns[i][p],
                               rw1, c + 1, tgs[i][p]);
                *reinterpret_cast<float2*>(&OUT[(size_t)row * C + c]) = o;
            }
    }
}

// ---------------------------------------------------------------------------
extern "C" void kernel_launch(void* const* d_in, const int* in_sizes, int n_in,
                              void* d_out, int out_size) {
    const float* x = (const float*)d_in[0];
    const long long* tgt = (const long long*)d_in[1];
    const float* w = (const float*)d_in[2];
    float* out = (float*)d_out;

    const int N = in_sizes[1];            // 512
    const int D = in_sizes[0] / N;        // 512
    const int C = in_sizes[2] / D;        // 100000

    zero_kernel<<<(CMAX + 255) / 256, 256>>>();
    xnorm_kernel<<<(N + 7) / 8, 256>>>(x, N, D);
    xconv_kernel<<<(N * D + 255) / 256, 256>>>(x, N * D);
    {
        dim3 tg2((C + 63) / 64, (D + 63) / 64);
        wtrans_kernel<<<tg2, 256>>>(w, D, C);
    }

    cudaFuncSetAttribute(gemm_epi_kernel,
                         cudaFuncAttributeMaxDynamicSharedMemorySize, SM_TOTAL);
    dim3 grid((N + BM - 1) / BM, (C + BN - 1) / BN);
    gemm_epi_kernel<<<grid, 256, SM_TOTAL>>>(tgt, out, N, D, C);
}

// round 10
// speedup vs baseline: 1.8939x; 1.0001x over previous
#include <cuda_runtime.h>
#include <cuda_fp16.h>
#include <math.h>
#include <stdint.h>

// ---------------------------------------------------------------------------
// AngleLinear (SphereFace A-Softmax forward, m=4, it=1) — mma.sync fp16
//   out[n,c] = clip( (x_n . w_c) / (|x_n| |w_c|), -1, 1 ) * |x_n|
//   out[n, target[n]] += (phi(c_t) - c_t) * |x_n| / (1 + lambda)
// R10: BK=64 (sync every 64 MMAs, 8 iters), 3-stage cp.async, 2 CTAs/SM
// (221KB smem/SM). Lean wtrans: norm folded into read phase, half2 writes.
// ---------------------------------------------------------------------------

#define PI_F 3.141592653f
#define INVL ((float)(1.0 / (1.0 + 1500.0 / 1.1)))

#define CMAX 100352
#define DMAX 512
#define NMAX 512

__device__ float g_wnorm2[CMAX];   // per-column sum of squares (atomic-folded)
__device__ float g_xnorm[NMAX];
__device__ __half g_Wh[(size_t)CMAX * DMAX];  // W^T [c][d], fp16
__device__ __half g_Ah[(size_t)NMAX * DMAX];  // x [n][d], fp16

// ---------------- PTX helpers (all sm_80-safe) ----------------
__device__ __forceinline__ uint32_t smem_u32(const void* p) {
    uint32_t a;
    asm("{ .reg .u64 t; cvta.to.shared.u64 t, %1; cvt.u32.u64 %0, t; }"
        : "=r"(a) : "l"(p));
    return a;
}
__device__ __forceinline__ void cp16(uint32_t dst, const void* src) {
    asm volatile("cp.async.cg.shared.global [%0], [%1], 16;"
                 :: "r"(dst), "l"(src));
}
#define CP_COMMIT() asm volatile("cp.async.commit_group;" ::: "memory")
#define CP_WAIT1() asm volatile("cp.async.wait_group 1;" ::: "memory")

__device__ __forceinline__ void ldsm4(uint32_t& r0, uint32_t& r1, uint32_t& r2,
                                      uint32_t& r3, uint32_t addr) {
    asm volatile("ldmatrix.sync.aligned.m8n8.x4.shared.b16 {%0,%1,%2,%3}, [%4];"
                 : "=r"(r0), "=r"(r1), "=r"(r2), "=r"(r3) : "r"(addr));
}
__device__ __forceinline__ void mma16816(float* c, const uint32_t* a,
                                         uint32_t b0, uint32_t b1) {
    asm volatile(
        "mma.sync.aligned.m16n8k16.row.col.f32.f16.f16.f32 "
        "{%0,%1,%2,%3}, {%4,%5,%6,%7}, {%8,%9}, {%0,%1,%2,%3};"
        : "+f"(c[0]), "+f"(c[1]), "+f"(c[2]), "+f"(c[3])
        : "r"(a[0]), "r"(a[1]), "r"(a[2]), "r"(a[3]), "r"(b0), "r"(b1));
}

// ---------------- pre-pass kernels ----------------
__global__ void zero_kernel() {
    int i = blockIdx.x * blockDim.x + threadIdx.x;
    if (i < CMAX) g_wnorm2[i] = 0.0f;
}

__global__ void xnorm_kernel(const float* __restrict__ X, int N, int D) {
    int warp = (blockIdx.x * blockDim.x + threadIdx.x) >> 5;
    int lane = threadIdx.x & 31;
    if (warp >= N) return;
    float s = 0.0f;
    for (int d = lane; d < D; d += 32) {
        float v = X[(size_t)warp * D + d];
        s = fmaf(v, v, s);
    }
#pragma unroll
    for (int o = 16; o > 0; o >>= 1) s += __shfl_down_sync(0xffffffffu, s, o);
    if (lane == 0) g_xnorm[warp] = sqrtf(s);
}

__global__ void xconv_kernel(const float* __restrict__ X, int total) {
    int i = blockIdx.x * blockDim.x + threadIdx.x;
    if (i >= total) return;
    g_Ah[i] = __float2half_rn(X[i]);
}

// W [D,C] f32 -> W^T [C,D] fp16 (64x64 tiles through SMEM).
// Column sum-of-squares folded into the read phase (register acc),
// half2-vectorized write phase.
__global__ void wtrans_kernel(const float* __restrict__ W, int D, int C) {
    __shared__ float s[64][65];
    __shared__ float sq[4][64];
    const int tid = threadIdx.x;
    const int c0 = blockIdx.x * 64;
    const int d0 = blockIdx.y * 64;

    const int cr = tid & 63;        // read-phase column (fixed per thread)
    const int dr = tid >> 6;        // read-phase row base (0..3)
    const int gc_r = c0 + cr;
    float acc = 0.0f;
#pragma unroll
    for (int i = 0; i < 16; i++) {
        int d = dr + 4 * i;
        float v = (gc_r < C) ? W[(size_t)(d0 + d) * C + gc_r] : 0.0f;
        s[d][cr] = v;
        acc = fmaf(v, v, acc);
    }
    sq[dr][cr] = acc;
    __syncthreads();

#pragma unroll
    for (int i = 0; i < 8; i++) {
        int e = tid + 256 * i;
        int c = e >> 5;              // 0..63
        int dp = (e & 31) * 2;       // even d
        int gc = c0 + c;
        if (gc < C) {
            __half2 h = __floats2half2_rn(s[dp][c], s[dp + 1][c]);
            *reinterpret_cast<__half2*>(&g_Wh[(size_t)gc * D + d0 + dp]) = h;
        }
    }
    if (tid < 64 && c0 + tid < C) {
        float t = (sq[0][tid] + sq[1][tid]) + (sq[2][tid] + sq[3][tid]);
        atomicAdd(&g_wnorm2[c0 + tid], t);
    }
}

// ---------------- epilogue math ----------------
__device__ __forceinline__ float epi_elem(float v, float rxn, float xn,
                                          float rwn, int c, long long tgt) {
    float cc = v * rxn * rwn;
    cc = fminf(1.0f, fmaxf(-1.0f, cc));
    float o = cc * xn;
    if ((long long)c == tgt) {
        float c2 = cc * cc;
        float cosm = fmaf(8.0f * c2, c2, fmaf(-8.0f, c2, 1.0f));
        float th = acosf(cc);
        float kf = floorf(th * (4.0f / PI_F));
        int ki = (int)kf;
        float sgn = (ki & 1) ? -1.0f : 1.0f;
        float phi = fmaf(sgn, cosm, -2.0f * kf);
        o += (phi - cc) * xn * INVL;
    }
    return o;
}

// ---------------- mma.sync GEMM + epilogue ----------------
// BM=128, BN=128, BK=64. 256 threads = 8 warps (4x2), warp tile 32x64.
// 2 CTAs/SM. PA=144 (128B data + 16 pad; 9r+ch mod 8 distinct -> ldmatrix
// conflict-free). 3-stage cp.async, 1 syncthreads per iter, 8 iters.
#define BM 128
#define BN 128
#define BK 64
#define PA 144
#define TILE_B (128 * PA)           // 18432 per tile (A or B)
#define STAGE_B (2 * TILE_B)        // 36864 per stage
#define STAGES 3
#define SM_TOTAL (STAGES * STAGE_B) // 110592 -> 2 CTAs/SM (221KB)

#define OFF_A 0
#define OFF_B TILE_B

__device__ __forceinline__ void load_stage(uint32_t base, int m0, int c0,
                                           int it, int D, int tid) {
    const int r = tid >> 1;               // 0..127
    const int chb = (tid & 1) * 4;        // chunks {0..3} or {4..7}
#pragma unroll
    for (int q = 0; q < 4; q++) {
        const uint32_t doff = (uint32_t)(r * PA + (chb + q) * 16);
        const size_t koff = (size_t)it * BK + (chb + q) * 8;
        cp16(base + OFF_A + doff, g_Ah + (size_t)(m0 + r) * D + koff);
        cp16(base + OFF_B + doff, g_Wh + (size_t)(c0 + r) * D + koff);
    }
}

__global__ void __launch_bounds__(256, 2)
gemm_epi_kernel(const long long* __restrict__ TGT, float* __restrict__ OUT,
                int N, int D, int C) {
    extern __shared__ char smem[];
    const uint32_t sb = smem_u32(smem);
    const int tid = threadIdx.x;
    const int wid = tid >> 5;
    const int l = tid & 31;
    const int wm = wid >> 1;         // 0..3 -> rows 32*wm
    const int wn = wid & 1;          // 0..1 -> cols 64*wn
    const int m0 = blockIdx.x * BM;  // x fastest: m-tiles share W tile in L2
    const int c0 = blockIdx.y * BN;

    // A ldmatrix (normal): rows 32wm + l%16, 16B col select by l/16
    const uint32_t a_off =
        (uint32_t)((32 * wm + (l & 15)) * PA + (l >> 4) * 16);
    // B ldmatrix (K-major): rows 64wn + l%8 + 8*(l/16), 16B col by (l>>3)&1
    const uint32_t b_off =
        (uint32_t)((64 * wn + (l & 7) + ((l >> 4) << 3)) * PA +
                   ((l >> 3) & 1) * 16);

    float acc[2][8][4];
#pragma unroll
    for (int i = 0; i < 2; i++)
#pragma unroll
        for (int j = 0; j < 8; j++)
#pragma unroll
            for (int q = 0; q < 4; q++) acc[i][j][q] = 0.0f;

    const int iters = D / BK;  // 8
    load_stage(sb, m0, c0, 0, D, tid);
    CP_COMMIT();
    load_stage(sb + STAGE_B, m0, c0, 1, D, tid);
    CP_COMMIT();

    for (int it = 0; it < iters; it++) {
        CP_WAIT1();          // stage it resident
        __syncthreads();     // stage (it+2)%3 free of readers
        if (it + 2 < iters)
            load_stage(sb + (uint32_t)((it + 2) % STAGES) * STAGE_B,
                       m0, c0, it + 2, D, tid);
        CP_COMMIT();

        const uint32_t base = sb + (uint32_t)(it % STAGES) * STAGE_B;
#pragma unroll
        for (int ks = 0; ks < 4; ks++) {
            const uint32_t ko = (uint32_t)(ks * 32);
            uint32_t ah[2][4];
            ldsm4(ah[0][0], ah[0][1], ah[0][2], ah[0][3],
                  base + OFF_A + a_off + ko);
            ldsm4(ah[1][0], ah[1][1], ah[1][2], ah[1][3],
                  base + OFF_A + a_off + ko + 16 * PA);

            uint32_t bh[8][2];
#pragma unroll
            for (int g = 0; g < 4; g++)
                ldsm4(bh[2 * g][0], bh[2 * g][1], bh[2 * g + 1][0],
                      bh[2 * g + 1][1],
                      base + OFF_B + b_off + ko + (uint32_t)g * (16 * PA));

#pragma unroll
            for (int i = 0; i < 2; i++)
#pragma unroll
                for (int j = 0; j < 8; j++)
                    mma16816(acc[i][j], ah[i], bh[j][0], bh[j][1]);
        }
    }

    // ---- epilogue ----
    const int base_m = m0 + 32 * wm + (l >> 2);
    float xns[2][2], rxns[2][2];
    long long tgs[2][2];
#pragma unroll
    for (int i = 0; i < 2; i++)
#pragma unroll
        for (int p = 0; p < 2; p++) {
            int row = base_m + 16 * i + 8 * p;  // always < N (N=512, BM exact)
            float xn = g_xnorm[row];
            xns[i][p] = xn;
            rxns[i][p] = 1.0f / xn;
            tgs[i][p] = TGT[row];
        }

#pragma unroll
    for (int j = 0; j < 8; j++) {
        const int c = c0 + 64 * wn + 8 * j + 2 * (l & 3);
        if (c >= C) continue;  // C even -> pair fully valid or fully out
        const float rw0 = rsqrtf(g_wnorm2[c]);
        const float rw1 = rsqrtf(g_wnorm2[c + 1]);
#pragma unroll
        for (int i = 0; i < 2; i++)
#pragma unroll
            for (int p = 0; p < 2; p++) {
                const int row = base_m + 16 * i + 8 * p;
                float2 o;
                o.x = epi_elem(acc[i][j][2 * p + 0], rxns[i][p], xns[i][p],
                               rw0, c, tgs[i][p]);
                o.y = epi_elem(acc[i][j][2 * p + 1], rxns[i][p], xns[i][p],
                               rw1, c + 1, tgs[i][p]);
                *reinterpret_cast<float2*>(&OUT[(size_t)row * C + c]) = o;
            }
    }
}

// ---------------------------------------------------------------------------
extern "C" void kernel_launch(void* const* d_in, const int* in_sizes, int n_in,
                              void* d_out, int out_size) {
    const float* x = (const float*)d_in[0];
    const long long* tgt = (const long long*)d_in[1];
    const float* w = (const float*)d_in[2];
    float* out = (float*)d_out;

    const int N = in_sizes[1];            // 512
    const int D = in_sizes[0] / N;        // 512
    const int C = in_sizes[2] / D;        // 100000

    zero_kernel<<<(CMAX + 255) / 256, 256>>>();
    xnorm_kernel<<<(N + 7) / 8, 256>>>(x, N, D);
    xconv_kernel<<<(N * D + 255) / 256, 256>>>(x, N * D);
    {
        dim3 tg2((C + 63) / 64, (D + 63) / 64);
        wtrans_kernel<<<tg2, 256>>>(w, D, C);
    }

    cudaFuncSetAttribute(gemm_epi_kernel,
                         cudaFuncAttributeMaxDynamicSharedMemorySize, SM_TOTAL);
    dim3 grid((N + BM - 1) / BM, (C + BN - 1) / BN);
    gemm_epi_kernel<<<grid, 256, SM_TOTAL>>>(tgt, out, N, D, C);
}